// round 11
// baseline (speedup 1.0000x reference)
#include <cuda_runtime.h>
#include <cstdint>

#define Bq 256
#define Nn 256
#define Dd 1024
#define Ss 1024

// K1 smem: per-warp double-buffered B slice [16 warps][2 buf][32 k][16 d]
// (XOR-swizzled 8-blocks) + epilogue reduction scratch.
#define OFF_RED 16384
#define SMEM_F (OFF_RED + 1152)
#define SMEM_BYTES (SMEM_F * 4)           // 70144 B (2 CTAs/SM -> 140 KB)

// Scratch (device globals — no allocation APIs anywhere)
__device__ float    g_A[Bq * Ss];
__device__ float    g_M[Bq * Nn];
__device__ uint32_t g_Ahi[Bq * Nn];        // A frags tf32 hi: [kg32][mt16][lane32][4]
__device__ uint32_t g_Alo[Bq * Nn];
__device__ float    g_stats[Bq * Bq * 32]; // per (i,b,nt 0..15): m, s
__device__ float    g_ctx_scratch[Bq * Dd];

// ---------------------------------------------------------------------------
__global__ void gemm_A_kernel(const float* __restrict__ state,
                              const float* __restrict__ Q) {
    __shared__ float sS[32][33];
    __shared__ float sQ[32][33];
    int tx = threadIdx.x, ty = threadIdx.y;
    int t = ty * 16 + tx;
    int b0 = blockIdx.y * 32, s0 = blockIdx.x * 32;
    float acc00 = 0.f, acc01 = 0.f, acc10 = 0.f, acc11 = 0.f;
    for (int k0 = 0; k0 < Ss; k0 += 32) {
        #pragma unroll
        for (int l = t; l < 1024; l += 256) {
            int r = l >> 5, c = l & 31;
            sS[r][c] = state[(b0 + r) * Ss + k0 + c];
            sQ[r][c] = Q[(s0 + r) * Ss + k0 + c];
        }
        __syncthreads();
        #pragma unroll
        for (int kk = 0; kk < 32; kk++) {
            float a0 = sS[2 * ty][kk],     a1 = sS[2 * ty + 1][kk];
            float q0 = sQ[2 * tx][kk],     q1 = sQ[2 * tx + 1][kk];
            acc00 = fmaf(a0, q0, acc00);
            acc01 = fmaf(a0, q1, acc01);
            acc10 = fmaf(a1, q0, acc10);
            acc11 = fmaf(a1, q1, acc11);
        }
        __syncthreads();
    }
    g_A[(b0 + 2 * ty)     * Ss + s0 + 2 * tx]     = acc00;
    g_A[(b0 + 2 * ty)     * Ss + s0 + 2 * tx + 1] = acc01;
    g_A[(b0 + 2 * ty + 1) * Ss + s0 + 2 * tx]     = acc10;
    g_A[(b0 + 2 * ty + 1) * Ss + s0 + 2 * tx + 1] = acc11;
}

__global__ void gemm_M_kernel(const float* __restrict__ Km) {
    __shared__ float sA[32][33];
    __shared__ float sK[32][33];
    int tx = threadIdx.x, ty = threadIdx.y;
    int t = ty * 16 + tx;
    int b0 = blockIdx.y * 32, n0 = blockIdx.x * 32;
    float acc00 = 0.f, acc01 = 0.f, acc10 = 0.f, acc11 = 0.f;
    for (int kc = 0; kc < Ss; kc += 32) {
        #pragma unroll
        for (int l = t; l < 1024; l += 256) {
            int r = l >> 5, c = l & 31;
            sA[r][c] = g_A[(b0 + r) * Ss + kc + c];
            sK[r][c] = Km[(kc + r) * Nn + n0 + c];
        }
        __syncthreads();
        #pragma unroll
        for (int kk = 0; kk < 32; kk++) {
            float a0 = sA[2 * ty][kk],     a1 = sA[2 * ty + 1][kk];
            float b0v = sK[kk][2 * tx],    b1v = sK[kk][2 * tx + 1];
            acc00 = fmaf(a0, b0v, acc00);
            acc01 = fmaf(a0, b1v, acc01);
            acc10 = fmaf(a1, b0v, acc10);
            acc11 = fmaf(a1, b1v, acc11);
        }
        __syncthreads();
    }
    g_M[(b0 + 2 * ty)     * Nn + n0 + 2 * tx]     = acc00;
    g_M[(b0 + 2 * ty)     * Nn + n0 + 2 * tx + 1] = acc01;
    g_M[(b0 + 2 * ty + 1) * Nn + n0 + 2 * tx]     = acc10;
    g_M[(b0 + 2 * ty + 1) * Nn + n0 + 2 * tx + 1] = acc11;
}

// ---------------------------------------------------------------------------
__device__ __forceinline__ void cp_async16(uint32_t saddr, const void* gptr) {
    asm volatile("cp.async.ca.shared.global [%0], [%1], 16;\n"
                 :: "r"(saddr), "l"(gptr));
}
__device__ __forceinline__ uint32_t f2tf(float x) {
    uint32_t r;
    asm("cvt.rna.tf32.f32 %0, %1;" : "=r"(r) : "f"(x));
    return r;
}
__device__ __forceinline__ void tfsplit(float x, uint32_t& hi, uint32_t& lo) {
    hi = f2tf(x);
    lo = f2tf(x - __uint_as_float(hi));
}
__device__ __forceinline__ void mma_tf32(float* c, const uint32_t* a,
                                         uint32_t b0, uint32_t b1) {
    asm volatile(
        "mma.sync.aligned.m16n8k8.row.col.f32.tf32.tf32.f32 "
        "{%0,%1,%2,%3}, {%4,%5,%6,%7}, {%8,%9}, {%0,%1,%2,%3};"
        : "+f"(c[0]), "+f"(c[1]), "+f"(c[2]), "+f"(c[3])
        : "r"(a[0]), "r"(a[1]), "r"(a[2]), "r"(a[3]), "r"(b0), "r"(b1));
}

// ---------------------------------------------------------------------------
// A pre-split: g_M -> tf32 hi/lo fragments [kg][mtile][lane][4]
__global__ void afrag_kernel() {
    int wg = blockIdx.x * 8 + (threadIdx.x >> 5);   // kg*16 + mtile
    int l  = threadIdx.x & 31;
    int m0 = (wg & 15) * 16 + (l >> 2);
    int k0 = (wg >> 4) * 8 + (l & 3);
    float x0 = g_M[m0 * Nn + k0];
    float x1 = g_M[(m0 + 8) * Nn + k0];
    float x2 = g_M[m0 * Nn + k0 + 4];
    float x3 = g_M[(m0 + 8) * Nn + k0 + 4];
    uint4 h, lo;
    tfsplit(x0, h.x, lo.x); tfsplit(x1, h.y, lo.y);
    tfsplit(x2, h.z, lo.z); tfsplit(x3, h.w, lo.w);
    *(uint4*)(g_Ahi + (size_t)(wg * 32 + l) * 4) = h;
    *(uint4*)(g_Alo + (size_t)(wg * 32 + l) * 4) = lo;
}

// ---------------------------------------------------------------------------
// K1: 3-pass tf32 mma.sync. CTA=(nt,mt,i): C[128 m][64 d], k=256 (8 chunks).
// BARRIER-FREE mainloop: each warp cp.asyncs its own 32k x 16d B slice into
// private smem (XOR-swizzled), waits only on its own cp groups, converts to
// tf32 hi/lo in registers, MMAs. Warps drift freely -> tensor pipe stays fed.
__global__ void __launch_bounds__(512, 2)
wpre_mma_kernel(const float* __restrict__ FV, float* __restrict__ Wout) {
    extern __shared__ float smem[];
    const int i  = blockIdx.z;
    const int mt = blockIdx.y;
    const int nt = blockIdx.x;
    const int b0 = mt * 128;
    const int d0 = nt * 64;
    const int tid = threadIdx.x;
    const int w = tid >> 5, l = tid & 31;
    const int mw = w & 3, nw = w >> 2;
    const float* FVi = FV + (size_t)i * Nn * Dd;
    const uint32_t sbase = (uint32_t)__cvta_generic_to_shared(smem);

    // warp-private slice base (floats): [w][buf][32 k][16 d]
    float* slice = smem + w * 1024;
    const uint32_t s_slice = sbase + (uint32_t)(w * 1024) * 4;

    // stage chunk c into own buf: lane l = row k; 4 x 16B chunks, XOR swizzle
    auto issue_stage = [&](int c) {
        const float* src = FVi + (size_t)(c * 32 + l) * Dd + d0 + nw * 16;
        uint32_t sw = ((uint32_t)l & 2u) << 2;        // 8-float XOR per k&2
        uint32_t sdst = s_slice + (uint32_t)((c & 1) * 512 + l * 16) * 4;
        #pragma unroll
        for (int d4 = 0; d4 < 4; d4++)
            cp_async16(sdst + (((uint32_t)(d4 * 4) ^ sw)) * 4, src + d4 * 4);
        asm volatile("cp.async.commit_group;\n");
    };

    issue_stage(0);

    float acc[2][2][4];
    #pragma unroll
    for (int a = 0; a < 2; a++)
        #pragma unroll
        for (int b = 0; b < 2; b++)
            #pragma unroll
            for (int c = 0; c < 4; c++) acc[a][b][c] = 0.f;

    const int lk = l & 3, ld = l >> 2;

    for (int c = 0; c < 8; c++) {
        if (c + 1 < 8) {
            issue_stage(c + 1);
            asm volatile("cp.async.wait_group 1;\n");   // chunk c ready
        } else {
            asm volatile("cp.async.wait_group 0;\n");
        }

        const float* buf = slice + (c & 1) * 512;
        #pragma unroll
        for (int ks = 0; ks < 4; ks++) {
            const int kg = c * 4 + ks;
            // A fragments via LDG (L1-resident, broadcast across nw warps)
            uint4 ah[2], al[2];
            #pragma unroll
            for (int mi = 0; mi < 2; mi++) {
                int mtile = mt * 8 + mw * 2 + mi;
                size_t aw = (size_t)((kg * 16 + mtile) * 32 + l) * 4;
                ah[mi] = *(const uint4*)(g_Ahi + aw);
                al[mi] = *(const uint4*)(g_Alo + aw);
            }
            // B from own slice: rows k0=ks*8+lk, k1=k0+4; cols ld, ld+8
            const int k0 = ks * 8 + lk;
            const int sw = (k0 & 2) ? 8 : 0;
            const float* r0 = buf + k0 * 16;
            const float* r1 = buf + (k0 + 4) * 16;
            #pragma unroll
            for (int j = 0; j < 2; j++) {
                int d = (j * 8 + ld) ^ sw;
                float x0 = r0[d];
                float x1 = r1[d];
                uint32_t bh0, bl0, bh1, bl1;
                tfsplit(x0, bh0, bl0);
                tfsplit(x1, bh1, bl1);
                #pragma unroll
                for (int mi = 0; mi < 2; mi++) {
                    mma_tf32(acc[mi][j], (const uint32_t*)&ah[mi], bh0, bh1);
                    mma_tf32(acc[mi][j], (const uint32_t*)&ah[mi], bl0, bl1);
                    mma_tf32(acc[mi][j], (const uint32_t*)&al[mi], bh0, bh1);
                }
            }
        }
    }
    __syncthreads();

    // ---- epilogue: per-row tile stats + pre-softmax W store
    float* fm   = smem + OFF_RED;
    float* redm = fm + 128;
    float* reds = redm + 512;

    #pragma unroll
    for (int mi = 0; mi < 2; mi++) {
        #pragma unroll
        for (int h = 0; h < 2; h++) {
            float m = -3.4e38f;
            #pragma unroll
            for (int j = 0; j < 2; j++)
                m = fmaxf(m, fmaxf(acc[mi][j][2 * h], acc[mi][j][2 * h + 1]));
            m = fmaxf(m, __shfl_xor_sync(0xffffffffu, m, 1));
            m = fmaxf(m, __shfl_xor_sync(0xffffffffu, m, 2));
            if ((l & 3) == 0)
                redm[nw * 128 + mw * 32 + mi * 16 + (l >> 2) + 8 * h] = m;
        }
    }
    __syncthreads();
    if (tid < 128)
        fm[tid] = fmaxf(fmaxf(redm[tid], redm[128 + tid]),
                        fmaxf(redm[256 + tid], redm[384 + tid]));
    __syncthreads();
    #pragma unroll
    for (int mi = 0; mi < 2; mi++) {
        #pragma unroll
        for (int h = 0; h < 2; h++) {
            int row = mw * 32 + mi * 16 + (l >> 2) + 8 * h;
            float m = fm[row];
            float s = 0.f;
            #pragma unroll
            for (int j = 0; j < 2; j++)
                s += __expf(acc[mi][j][2 * h] - m) + __expf(acc[mi][j][2 * h + 1] - m);
            s += __shfl_xor_sync(0xffffffffu, s, 1);
            s += __shfl_xor_sync(0xffffffffu, s, 2);
            if ((l & 3) == 0) reds[nw * 128 + row] = s;
        }
    }
    __syncthreads();
    if (tid < 128) {
        int sidx = (((i * Bq) + b0 + tid) * 16 + nt) * 2;
        g_stats[sidx]     = fm[tid];
        g_stats[sidx + 1] = (reds[tid] + reds[128 + tid])
                          + (reds[256 + tid] + reds[384 + tid]);
    }
    #pragma unroll
    for (int mi = 0; mi < 2; mi++) {
        #pragma unroll
        for (int h = 0; h < 2; h++) {
            int row = mw * 32 + mi * 16 + (l >> 2) + 8 * h;
            float* wr = Wout + ((size_t)i * Bq + b0 + row) * Dd
                      + d0 + nw * 16 + 2 * (l & 3);
            #pragma unroll
            for (int j = 0; j < 2; j++)
                *(float2*)(wr + j * 8) =
                    make_float2(acc[mi][j][2 * h], acc[mi][j][2 * h + 1]);
        }
    }
}

// ---------------------------------------------------------------------------
// K2: combine 16 tile-stats per row, softmax W in place, accumulate context.
__global__ void __launch_bounds__(512, 2)
softmax_ctx_kernel(const float* __restrict__ FV,
                   float* __restrict__ W,
                   float* __restrict__ ctx) {
    __shared__ float sm_m[256], sm_inv[256];
    const int i = blockIdx.y;
    const int d = blockIdx.x * 512 + threadIdx.x;
    if (threadIdx.x < 256) {
        int b = threadIdx.x;
        const float* st = g_stats + (size_t)(i * Bq + b) * 32;
        float m = st[0];
        #pragma unroll
        for (int t = 1; t < 16; t++) m = fmaxf(m, st[2 * t]);
        float s = 0.f;
        #pragma unroll
        for (int t = 0; t < 16; t++) s += st[2 * t + 1] * __expf(st[2 * t] - m);
        sm_m[b] = m;
        sm_inv[b] = 1.f / s;
    }
    __syncthreads();
    float acc = 0.f;
    const float* FVi = FV + (size_t)i * Nn * Dd + d;
    float* Wi = W + (size_t)i * Bq * Dd + d;
    #pragma unroll 4
    for (int b = 0; b < Bq; b++) {
        float x = Wi[(size_t)b * Dd];
        float w = __expf(x - sm_m[b]) * sm_inv[b];
        Wi[(size_t)b * Dd] = w;
        acc = fmaf(w, FVi[(size_t)b * Dd], acc);
    }
    ctx[(size_t)i * Dd + d] = acc;
}

// ---------------------------------------------------------------------------
extern "C" void kernel_launch(void* const* d_in, const int* in_sizes, int n_in,
                              void* d_out, int out_size) {
    const float* FV    = (const float*)d_in[0];
    const float* state = (const float*)d_in[1];
    const float* Q     = (const float*)d_in[2];
    const float* Km    = (const float*)d_in[3];
    float* out = (float*)d_out;

    const long long wsz = (long long)Bq * Bq * Dd;
    float* ctxp;
    float* Wp;
    if ((long long)out_size == wsz) {
        Wp = out;
        cudaGetSymbolAddress((void**)&ctxp, g_ctx_scratch);
    } else {
        ctxp = out;
        Wp   = out + (size_t)Bq * Dd;
    }

    cudaFuncSetAttribute(wpre_mma_kernel,
                         cudaFuncAttributeMaxDynamicSharedMemorySize, SMEM_BYTES);

    gemm_A_kernel<<<dim3(Ss / 32, Bq / 32), dim3(16, 16)>>>(state, Q);
    gemm_M_kernel<<<dim3(Nn / 32, Bq / 32), dim3(16, 16)>>>(Km);
    afrag_kernel<<<64, 256>>>();
    wpre_mma_kernel<<<dim3(16, 2, 256), 512, SMEM_BYTES>>>(FV, Wp);
    softmax_ctx_kernel<<<dim3(2, 256), 512>>>(FV, Wp, ctxp);
}

// round 12
// speedup vs baseline: 1.4509x; 1.4509x over previous
#include <cuda_runtime.h>
#include <cstdint>

#define Bq 256
#define Nn 256
#define Dd 1024
#define Ss 1024

// K1 tiling (R6-proven)
#define STG_P 132
#define OFF_STAGE 0
#define STAGE_F (2 * 32 * STG_P)       // 8448
#define OFF_BFH STAGE_F                // B frags hi: 4 ks * 8 jp * 32 * 4 = 4096
#define OFF_BFL (OFF_BFH + 4096)
#define OFF_RED (OFF_BFL + 4096)       // fm[128] + redm[4][128] + reds[4][128]
#define SMEM_F (OFF_RED + 1152)
#define SMEM_BYTES (SMEM_F * 4)        // 71168 B

// Scratch (device globals — no allocation APIs anywhere)
__device__ float    g_A[Bq * Ss];
__device__ float    g_M[Bq * Nn];
__device__ uint32_t g_Ahi[Bq * Nn];       // A fragments, tf32 hi
__device__ uint32_t g_Alo[Bq * Nn];       // A fragments, tf32 lo
__device__ float    g_stats[Bq * Bq * 16]; // per (i,b,nt 0..7): m, s
__device__ float    g_ctx_scratch[Bq * Dd];

// ---------------------------------------------------------------------------
__global__ void gemm_A_kernel(const float* __restrict__ state,
                              const float* __restrict__ Q) {
    __shared__ float sS[32][33];
    __shared__ float sQ[32][33];
    int tx = threadIdx.x, ty = threadIdx.y;
    int t = ty * 16 + tx;
    int b0 = blockIdx.y * 32, s0 = blockIdx.x * 32;
    float acc00 = 0.f, acc01 = 0.f, acc10 = 0.f, acc11 = 0.f;
    for (int k0 = 0; k0 < Ss; k0 += 32) {
        #pragma unroll
        for (int l = t; l < 1024; l += 256) {
            int r = l >> 5, c = l & 31;
            sS[r][c] = state[(b0 + r) * Ss + k0 + c];
            sQ[r][c] = Q[(s0 + r) * Ss + k0 + c];
        }
        __syncthreads();
        #pragma unroll
        for (int kk = 0; kk < 32; kk++) {
            float a0 = sS[2 * ty][kk],     a1 = sS[2 * ty + 1][kk];
            float q0 = sQ[2 * tx][kk],     q1 = sQ[2 * tx + 1][kk];
            acc00 = fmaf(a0, q0, acc00);
            acc01 = fmaf(a0, q1, acc01);
            acc10 = fmaf(a1, q0, acc10);
            acc11 = fmaf(a1, q1, acc11);
        }
        __syncthreads();
    }
    g_A[(b0 + 2 * ty)     * Ss + s0 + 2 * tx]     = acc00;
    g_A[(b0 + 2 * ty)     * Ss + s0 + 2 * tx + 1] = acc01;
    g_A[(b0 + 2 * ty + 1) * Ss + s0 + 2 * tx]     = acc10;
    g_A[(b0 + 2 * ty + 1) * Ss + s0 + 2 * tx + 1] = acc11;
}

__global__ void gemm_M_kernel(const float* __restrict__ Km) {
    __shared__ float sA[32][33];
    __shared__ float sK[32][33];
    int tx = threadIdx.x, ty = threadIdx.y;
    int t = ty * 16 + tx;
    int b0 = blockIdx.y * 32, n0 = blockIdx.x * 32;
    float acc00 = 0.f, acc01 = 0.f, acc10 = 0.f, acc11 = 0.f;
    for (int kc = 0; kc < Ss; kc += 32) {
        #pragma unroll
        for (int l = t; l < 1024; l += 256) {
            int r = l >> 5, c = l & 31;
            sA[r][c] = g_A[(b0 + r) * Ss + kc + c];
            sK[r][c] = Km[(kc + r) * Nn + n0 + c];
        }
        __syncthreads();
        #pragma unroll
        for (int kk = 0; kk < 32; kk++) {
            float a0 = sA[2 * ty][kk],     a1 = sA[2 * ty + 1][kk];
            float b0v = sK[kk][2 * tx],    b1v = sK[kk][2 * tx + 1];
            acc00 = fmaf(a0, b0v, acc00);
            acc01 = fmaf(a0, b1v, acc01);
            acc10 = fmaf(a1, b0v, acc10);
            acc11 = fmaf(a1, b1v, acc11);
        }
        __syncthreads();
    }
    g_M[(b0 + 2 * ty)     * Nn + n0 + 2 * tx]     = acc00;
    g_M[(b0 + 2 * ty)     * Nn + n0 + 2 * tx + 1] = acc01;
    g_M[(b0 + 2 * ty + 1) * Nn + n0 + 2 * tx]     = acc10;
    g_M[(b0 + 2 * ty + 1) * Nn + n0 + 2 * tx + 1] = acc11;
}

// ---------------------------------------------------------------------------
__device__ __forceinline__ void cp_async16(uint32_t saddr, const void* gptr) {
    asm volatile("cp.async.cg.shared.global [%0], [%1], 16;\n"
                 :: "r"(saddr), "l"(gptr));
}
__device__ __forceinline__ uint32_t f2tf(float x) {
    uint32_t r;
    asm("cvt.rna.tf32.f32 %0, %1;" : "=r"(r) : "f"(x));
    return r;
}
__device__ __forceinline__ void tfsplit(float x, uint32_t& hi, uint32_t& lo) {
    hi = f2tf(x);
    lo = f2tf(x - __uint_as_float(hi));
}
__device__ __forceinline__ void mma_tf32(float* c, const uint32_t* a,
                                         uint32_t b0, uint32_t b1) {
    asm volatile(
        "mma.sync.aligned.m16n8k8.row.col.f32.tf32.tf32.f32 "
        "{%0,%1,%2,%3}, {%4,%5,%6,%7}, {%8,%9}, {%0,%1,%2,%3};"
        : "+f"(c[0]), "+f"(c[1]), "+f"(c[2]), "+f"(c[3])
        : "r"(a[0]), "r"(a[1]), "r"(a[2]), "r"(a[3]), "r"(b0), "r"(b1));
}

// ---------------------------------------------------------------------------
// A pre-split: g_M -> tf32 hi/lo in mma fragment order.
__global__ void afrag_kernel() {
    int wg = blockIdx.x * 8 + (threadIdx.x >> 5);   // kg*16 + mtile
    int l  = threadIdx.x & 31;
    int m0 = (wg & 15) * 16 + (l >> 2);
    int k0 = (wg >> 4) * 8 + (l & 3);
    float x0 = g_M[m0 * Nn + k0];
    float x1 = g_M[(m0 + 8) * Nn + k0];
    float x2 = g_M[m0 * Nn + k0 + 4];
    float x3 = g_M[(m0 + 8) * Nn + k0 + 4];
    uint4 h, lo;
    tfsplit(x0, h.x, lo.x); tfsplit(x1, h.y, lo.y);
    tfsplit(x2, h.z, lo.z); tfsplit(x3, h.w, lo.w);
    *(uint4*)(g_Ahi + (size_t)(wg * 32 + l) * 4) = h;
    *(uint4*)(g_Alo + (size_t)(wg * 32 + l) * 4) = lo;
}

// ---------------------------------------------------------------------------
// K1 (R6 verbatim): 3-pass tf32 mma.sync. CTA=(nt,mt,i): C[128 m][128 d],
// k=256 in 8 chunks. 16 warps as 4m x 4n, warp tile 32x32.
__global__ void __launch_bounds__(512, 1)
wpre_mma_kernel(const float* __restrict__ FV, float* __restrict__ Wout) {
    extern __shared__ float smem[];
    uint32_t* smu = (uint32_t*)smem;
    const int i  = blockIdx.z;
    const int mt = blockIdx.y;
    const int nt = blockIdx.x;
    const int b0 = mt * 128;
    const int d0 = nt * 128;
    const int tid = threadIdx.x;
    const int w = tid >> 5, l = tid & 31;
    const int mw = w & 3, nw = w >> 2;
    const int cks = w >> 2, cjp = (w & 3) * 2;
    const float* FVi = FV + (size_t)i * Nn * Dd;
    const uint32_t sbase = (uint32_t)__cvta_generic_to_shared(smem);

    #pragma unroll
    for (int k = 0; k < 2; k++) {
        int v = tid + 512 * k;
        int r = v >> 5, c4 = v & 31;
        cp_async16(sbase + (uint32_t)(r * STG_P + c4 * 4) * 4,
                   FVi + (size_t)r * Dd + d0 + c4 * 4);
    }
    asm volatile("cp.async.commit_group;\n");

    float acc[2][4][4];
    #pragma unroll
    for (int a = 0; a < 2; a++)
        #pragma unroll
        for (int b = 0; b < 4; b++)
            #pragma unroll
            for (int c = 0; c < 4; c++) acc[a][b][c] = 0.f;

    for (int c = 0; c < 8; c++) {
        if (c + 1 < 8) {
            const float* src = FVi + (size_t)(c + 1) * 32 * Dd + d0;
            uint32_t dst = sbase + (uint32_t)(((c + 1) & 1) * 32 * STG_P) * 4;
            #pragma unroll
            for (int k = 0; k < 2; k++) {
                int v = tid + 512 * k;
                int r = v >> 5, c4 = v & 31;
                cp_async16(dst + (uint32_t)(r * STG_P + c4 * 4) * 4,
                           src + (size_t)r * Dd + c4 * 4);
            }
            asm volatile("cp.async.commit_group;\n");
            asm volatile("cp.async.wait_group 1;\n");
        } else {
            asm volatile("cp.async.wait_group 0;\n");
        }
        __syncthreads();

        const float* stg = smem + OFF_STAGE + (c & 1) * 32 * STG_P;
        #pragma unroll
        for (int jj = 0; jj < 2; jj++) {
            int jp = cjp + jj;
            uint4 h, lo;
            #pragma unroll
            for (int sub = 0; sub < 4; sub++) {
                int j = jp * 2 + (sub >> 1);
                int r = sub & 1;
                int k = cks * 8 + r * 4 + (l & 3);
                int d = j * 8 + (l >> 2);
                float x = stg[k * STG_P + d];
                tfsplit(x, ((uint32_t*)&h)[sub], ((uint32_t*)&lo)[sub]);
            }
            int word = ((cks * 8 + jp) * 32 + l) * 4;
            *(uint4*)(smu + OFF_BFH + word) = h;
            *(uint4*)(smu + OFF_BFL + word) = lo;
        }
        __syncthreads();

        #pragma unroll
        for (int ks = 0; ks < 4; ks++) {
            const int kg = c * 4 + ks;
            uint4 ah[2], al[2];
            #pragma unroll
            for (int mi = 0; mi < 2; mi++) {
                int mtile = mt * 8 + mw * 2 + mi;
                size_t aw = (size_t)((kg * 16 + mtile) * 32 + l) * 4;
                ah[mi] = *(const uint4*)(g_Ahi + aw);
                al[mi] = *(const uint4*)(g_Alo + aw);
            }
            uint4 bh[2], bl[2];
            #pragma unroll
            for (int p = 0; p < 2; p++) {
                int word = ((ks * 8 + nw * 2 + p) * 32 + l) * 4;
                bh[p] = *(const uint4*)(smu + OFF_BFH + word);
                bl[p] = *(const uint4*)(smu + OFF_BFL + word);
            }
            #pragma unroll
            for (int mi = 0; mi < 2; mi++) {
                #pragma unroll
                for (int j = 0; j < 4; j++) {
                    int p = j >> 1, hf = j & 1;
                    uint32_t bh0 = hf ? bh[p].z : bh[p].x;
                    uint32_t bh1 = hf ? bh[p].w : bh[p].y;
                    uint32_t bl0 = hf ? bl[p].z : bl[p].x;
                    uint32_t bl1 = hf ? bl[p].w : bl[p].y;
                    mma_tf32(acc[mi][j], (const uint32_t*)&ah[mi], bh0, bh1);
                    mma_tf32(acc[mi][j], (const uint32_t*)&ah[mi], bl0, bl1);
                    mma_tf32(acc[mi][j], (const uint32_t*)&al[mi], bh0, bh1);
                }
            }
        }
        __syncthreads();
    }
    __syncthreads();

    float* fm   = smem + OFF_RED;
    float* redm = fm + 128;
    float* reds = redm + 512;

    #pragma unroll
    for (int mi = 0; mi < 2; mi++) {
        #pragma unroll
        for (int h = 0; h < 2; h++) {
            float m = -3.4e38f;
            #pragma unroll
            for (int j = 0; j < 4; j++)
                m = fmaxf(m, fmaxf(acc[mi][j][2 * h], acc[mi][j][2 * h + 1]));
            m = fmaxf(m, __shfl_xor_sync(0xffffffffu, m, 1));
            m = fmaxf(m, __shfl_xor_sync(0xffffffffu, m, 2));
            if ((l & 3) == 0)
                redm[nw * 128 + mw * 32 + mi * 16 + (l >> 2) + 8 * h] = m;
        }
    }
    __syncthreads();
    if (tid < 128)
        fm[tid] = fmaxf(fmaxf(redm[tid], redm[128 + tid]),
                        fmaxf(redm[256 + tid], redm[384 + tid]));
    __syncthreads();
    #pragma unroll
    for (int mi = 0; mi < 2; mi++) {
        #pragma unroll
        for (int h = 0; h < 2; h++) {
            int row = mw * 32 + mi * 16 + (l >> 2) + 8 * h;
            float m = fm[row];
            float s = 0.f;
            #pragma unroll
            for (int j = 0; j < 4; j++)
                s += __expf(acc[mi][j][2 * h] - m) + __expf(acc[mi][j][2 * h + 1] - m);
            s += __shfl_xor_sync(0xffffffffu, s, 1);
            s += __shfl_xor_sync(0xffffffffu, s, 2);
            if ((l & 3) == 0) reds[nw * 128 + row] = s;
        }
    }
    __syncthreads();
    if (tid < 128) {
        int sidx = (((i * Bq) + b0 + tid) * 8 + nt) * 2;
        g_stats[sidx]     = fm[tid];
        g_stats[sidx + 1] = (reds[tid] + reds[128 + tid])
                          + (reds[256 + tid] + reds[384 + tid]);
    }
    #pragma unroll
    for (int mi = 0; mi < 2; mi++) {
        #pragma unroll
        for (int h = 0; h < 2; h++) {
            int row = mw * 32 + mi * 16 + (l >> 2) + 8 * h;
            float* wr = Wout + ((size_t)i * Bq + b0 + row) * Dd
                      + d0 + nw * 32 + 2 * (l & 3);
            #pragma unroll
            for (int j = 0; j < 4; j++)
                *(float2*)(wr + j * 8) =
                    make_float2(acc[mi][j][2 * h], acc[mi][j][2 * h + 1]);
        }
    }
}

// ---------------------------------------------------------------------------
// K2 (rebuilt): float4 streaming, 4-way b-split for MLP, ldcs/stcs hints.
// CTA = (dh, i): dh selects d-half (512 cols). 512 thr = 4 b-groups x 128.
__global__ void __launch_bounds__(512, 2)
softmax_ctx_kernel(const float* __restrict__ FV,
                   float* __restrict__ W,
                   float* __restrict__ ctx) {
    __shared__ float  sm_m[256], sm_inv[256];
    __shared__ float4 cpart[4][128];
    const int i  = blockIdx.y;
    const int dh = blockIdx.x;
    const int t  = threadIdx.x;
    const int g  = t >> 7;          // b-group 0..3
    const int tl = t & 127;
    const int d  = dh * 512 + tl * 4;

    if (t < 256) {
        int b = t;
        const float* st = g_stats + (size_t)(i * Bq + b) * 16;
        float m = st[0];
        #pragma unroll
        for (int k = 1; k < 8; k++) m = fmaxf(m, st[2 * k]);
        float s = 0.f;
        #pragma unroll
        for (int k = 0; k < 8; k++) s += st[2 * k + 1] * __expf(st[2 * k] - m);
        sm_m[b]   = m;
        sm_inv[b] = 1.f / s;
    }
    __syncthreads();

    const float4* Wv  = (const float4*)(W  + (size_t)i * Bq * Dd + d);
    float4*       Wo  = (float4*)(W  + (size_t)i * Bq * Dd + d);
    const float4* FVv = (const float4*)(FV + (size_t)i * Nn * Dd + d);
    const int strd = Dd / 4;

    float4 acc = make_float4(0.f, 0.f, 0.f, 0.f);
    #pragma unroll 4
    for (int it = 0; it < 64; it++) {
        int b = g + it * 4;
        float4 x = __ldcs(Wv + (size_t)b * strd);
        float m = sm_m[b], inv = sm_inv[b];
        float4 wv;
        wv.x = __expf(x.x - m) * inv;
        wv.y = __expf(x.y - m) * inv;
        wv.z = __expf(x.z - m) * inv;
        wv.w = __expf(x.w - m) * inv;
        __stcs(Wo + (size_t)b * strd, wv);
        float4 f = __ldcs(FVv + (size_t)b * strd);
        acc.x = fmaf(wv.x, f.x, acc.x);
        acc.y = fmaf(wv.y, f.y, acc.y);
        acc.z = fmaf(wv.z, f.z, acc.z);
        acc.w = fmaf(wv.w, f.w, acc.w);
    }
    cpart[g][tl] = acc;
    __syncthreads();
    if (g == 0) {
        float4 a0 = cpart[0][tl], a1 = cpart[1][tl];
        float4 a2 = cpart[2][tl], a3 = cpart[3][tl];
        float4 r;
        r.x = (a0.x + a1.x) + (a2.x + a3.x);
        r.y = (a0.y + a1.y) + (a2.y + a3.y);
        r.z = (a0.z + a1.z) + (a2.z + a3.z);
        r.w = (a0.w + a1.w) + (a2.w + a3.w);
        *(float4*)(ctx + (size_t)i * Dd + d) = r;
    }
}

// ---------------------------------------------------------------------------
extern "C" void kernel_launch(void* const* d_in, const int* in_sizes, int n_in,
                              void* d_out, int out_size) {
    const float* FV    = (const float*)d_in[0];
    const float* state = (const float*)d_in[1];
    const float* Q     = (const float*)d_in[2];
    const float* Km    = (const float*)d_in[3];
    float* out = (float*)d_out;

    const long long wsz = (long long)Bq * Bq * Dd;
    float* ctxp;
    float* Wp;
    if ((long long)out_size == wsz) {
        Wp = out;
        cudaGetSymbolAddress((void**)&ctxp, g_ctx_scratch);
    } else {
        ctxp = out;
        Wp   = out + (size_t)Bq * Dd;
    }

    cudaFuncSetAttribute(wpre_mma_kernel,
                         cudaFuncAttributeMaxDynamicSharedMemorySize, SMEM_BYTES);

    gemm_A_kernel<<<dim3(Ss / 32, Bq / 32), dim3(16, 16)>>>(state, Q);
    gemm_M_kernel<<<dim3(Nn / 32, Bq / 32), dim3(16, 16)>>>(Km);
    afrag_kernel<<<64, 256>>>();
    wpre_mma_kernel<<<dim3(8, 2, 256), 512, SMEM_BYTES>>>(FV, Wp);
    softmax_ctx_kernel<<<dim3(2, 256), 512>>>(FV, Wp, ctxp);
}